// round 2
// baseline (speedup 1.0000x reference)
#include <cuda_runtime.h>
#include <math.h>

// Problem constants (fixed shapes: B=4096, D=512, V=50000)
#define D      512
#define EPS    1e-8f
#define NEGINF -1e30f

#define BM 128
#define BN 128
#define BK 16

#define MAXB   4096
#define MAXV   50048
#define MAXNC  400     // ceil(50000/128) = 391

// -------- scratch (device globals; no allocation allowed) --------
__device__ float g_inn [MAXB * D];            // normalized input  (8 MB)
__device__ float g_vnn [MAXV * D];            // normalized veclist (~102 MB)
__device__ float g_dpos[MAXB];
__device__ float g_cval[MAXB * MAXNC * 2];    // per-(row,chunk) top-2 values
__device__ int   g_cidx[MAXB * MAXNC * 2];    // per-(row,chunk) top-2 indices
__device__ int   g_sel [MAXB * 2];            // final top-2 indices per row

__device__ __forceinline__ float warpSum(float v) {
#pragma unroll
    for (int o = 16; o > 0; o >>= 1) v += __shfl_down_sync(0xffffffffu, v, o);
    return v;
}

// ---------------- prep: normalize input rows, compute d_pos ----------------
__global__ void prep_input_kernel(const float* __restrict__ in,
                                  const float* __restrict__ tgt) {
    __shared__ float sbuf[3][4];
    int b = blockIdx.x;
    int t = threadIdx.x;                       // 128 threads, one float4 each
    const float4* ip = (const float4*)(in  + (size_t)b * D);
    const float4* tp = (const float4*)(tgt + (size_t)b * D);
    float4 iv = ip[t], tv = tp[t];
    float ii = iv.x*iv.x + iv.y*iv.y + iv.z*iv.z + iv.w*iv.w;
    float tt = tv.x*tv.x + tv.y*tv.y + tv.z*tv.z + tv.w*tv.w;
    float it = iv.x*tv.x + iv.y*tv.y + iv.z*tv.z + iv.w*tv.w;
    ii = warpSum(ii); tt = warpSum(tt); it = warpSum(it);
    int w = t >> 5, l = t & 31;
    if (l == 0) { sbuf[0][w] = ii; sbuf[1][w] = tt; sbuf[2][w] = it; }
    __syncthreads();
    float s_ii = sbuf[0][0] + sbuf[0][1] + sbuf[0][2] + sbuf[0][3];
    float s_tt = sbuf[1][0] + sbuf[1][1] + sbuf[1][2] + sbuf[1][3];
    float s_it = sbuf[2][0] + sbuf[2][1] + sbuf[2][2] + sbuf[2][3];
    float ni  = fmaxf(sqrtf(s_ii), EPS);
    float inv = 1.0f / ni;
    float4 o;
    o.x = iv.x * inv; o.y = iv.y * inv; o.z = iv.z * inv; o.w = iv.w * inv;
    ((float4*)(g_inn + (size_t)b * D))[t] = o;
    if (t == 0) {
        float nt  = fmaxf(sqrtf(s_tt), EPS);
        float sim = s_it / (ni * nt);
        g_dpos[b] = sqrtf(fmaxf(2.0f * (1.0f - sim), 1e-12f));
    }
}

// ---------------- prep: normalize veclist rows ----------------
__global__ void prep_vec_kernel(const float* __restrict__ vl, int V) {
    __shared__ float sbuf[4];
    int v = blockIdx.x;
    if (v >= V) return;
    int t = threadIdx.x;                       // 128 threads
    const float4* vp = (const float4*)(vl + (size_t)v * D);
    float4 x = vp[t];
    float nn = x.x*x.x + x.y*x.y + x.z*x.z + x.w*x.w;
    nn = warpSum(nn);
    int w = t >> 5, l = t & 31;
    if (l == 0) sbuf[w] = nn;
    __syncthreads();
    float s = sbuf[0] + sbuf[1] + sbuf[2] + sbuf[3];
    float inv = 1.0f / fmaxf(sqrtf(s), EPS);
    float4 o;
    o.x = x.x * inv; o.y = x.y * inv; o.z = x.z * inv; o.w = x.w * inv;
    ((float4*)(g_vnn + (size_t)v * D))[t] = o;
}

// ---------------- fused GEMM + per-chunk top-2 ----------------
struct Cand { float v0, v1; int i0, i1; };

__global__ __launch_bounds__(256, 2)
void gemm_topk_kernel(int V, int NC) {
    // As/Bs (16 KB) are dead after the k-loop; Cand table (32 KB) aliases them.
    __shared__ __align__(16) char smembuf[32768];
    float (*As)[BM] = reinterpret_cast<float (*)[BM]>(smembuf);
    float (*Bs)[BN] = reinterpret_cast<float (*)[BN]>(smembuf + BK * BM * 4);
    Cand  (*sc)[16] = reinterpret_cast<Cand  (*)[16]>(smembuf);

    const int bx = blockIdx.x;                 // V chunk
    const int by = blockIdx.y;                 // B chunk
    const int tid = threadIdx.x;
    const int tx = tid & 15, ty = tid >> 4;
    const int m0 = by * BM, n0 = bx * BN;

    float acc[8][8];
#pragma unroll
    for (int i = 0; i < 8; i++)
#pragma unroll
        for (int j = 0; j < 8; j++) acc[i][j] = 0.0f;

    for (int k0 = 0; k0 < D; k0 += BK) {
        // load A tile (128x16) -> As[k][m]; 512 float4 over 256 threads
#pragma unroll
        for (int i = 0; i < 2; i++) {
            int e = tid + i * 256;
            int row = e >> 2, kq = e & 3;
            float4 v = *(const float4*)(g_inn + (size_t)(m0 + row) * D + k0 + kq * 4);
            As[kq*4+0][row] = v.x; As[kq*4+1][row] = v.y;
            As[kq*4+2][row] = v.z; As[kq*4+3][row] = v.w;
        }
        // load B tile (128x16) -> Bs[k][n], zero-padded past V
#pragma unroll
        for (int i = 0; i < 2; i++) {
            int e = tid + i * 256;
            int row = e >> 2, kq = e & 3;
            int vr = n0 + row;
            float4 v = (vr < V)
                ? *(const float4*)(g_vnn + (size_t)vr * D + k0 + kq * 4)
                : make_float4(0.f, 0.f, 0.f, 0.f);
            Bs[kq*4+0][row] = v.x; Bs[kq*4+1][row] = v.y;
            Bs[kq*4+2][row] = v.z; Bs[kq*4+3][row] = v.w;
        }
        __syncthreads();
#pragma unroll
        for (int k = 0; k < BK; k++) {
            float a[8], b[8];
            float4 a0 = *(const float4*)&As[k][ty * 8];
            float4 a1 = *(const float4*)&As[k][ty * 8 + 4];
            float4 b0 = *(const float4*)&Bs[k][tx * 8];
            float4 b1 = *(const float4*)&Bs[k][tx * 8 + 4];
            a[0]=a0.x; a[1]=a0.y; a[2]=a0.z; a[3]=a0.w;
            a[4]=a1.x; a[5]=a1.y; a[6]=a1.z; a[7]=a1.w;
            b[0]=b0.x; b[1]=b0.y; b[2]=b0.z; b[3]=b0.w;
            b[4]=b1.x; b[5]=b1.y; b[6]=b1.z; b[7]=b1.w;
#pragma unroll
            for (int i = 0; i < 8; i++)
#pragma unroll
                for (int j = 0; j < 8; j++)
                    acc[i][j] = fmaf(a[i], b[j], acc[i][j]);
        }
        __syncthreads();
    }

    // per-thread top-2 over its 8 columns, for each of its 8 rows
#pragma unroll
    for (int i = 0; i < 8; i++) {
        float v0 = NEGINF, v1 = NEGINF; int i0 = -1, i1 = -1;
#pragma unroll
        for (int j = 0; j < 8; j++) {
            int col = n0 + tx * 8 + j;
            float v = (col < V) ? acc[i][j] : NEGINF;
            if (v > v0)      { v1 = v0; i1 = i0; v0 = v; i0 = col; }
            else if (v > v1) { v1 = v;  i1 = col; }
        }
        Cand c; c.v0 = v0; c.v1 = v1; c.i0 = i0; c.i1 = i1;
        sc[ty * 8 + i][tx] = c;
    }
    __syncthreads();

    // merge 16 partial top-2s per row; one thread per row
    if (tid < BM) {
        float v0 = NEGINF, v1 = NEGINF; int i0 = -1, i1 = -1;
        for (int q = 0; q < 16; q++) {
            Cand c = sc[tid][q];
            if (c.v0 > v0) {
                v1 = v0; i1 = i0; v0 = c.v0; i0 = c.i0;
                if (c.v1 > v1) { v1 = c.v1; i1 = c.i1; }
            } else if (c.v0 > v1) { v1 = c.v0; i1 = c.i0; }
        }
        int gr = m0 + tid;
        size_t base = ((size_t)gr * NC + bx) * 2;
        g_cval[base] = v0; g_cidx[base] = i0;
        g_cval[base + 1] = v1; g_cidx[base + 1] = i1;
    }
}

// ---------------- merge chunk candidates -> global top-2 per row ----------------
__global__ void reduce_topk_kernel(int NC) {
    __shared__ float sv0[256], sv1[256];
    __shared__ int   si0[256], si1[256];
    int b = blockIdx.x, t = threadIdx.x;
    int n = NC * 2;
    float v0 = NEGINF, v1 = NEGINF; int i0 = -1, i1 = -1;
    size_t base = (size_t)b * NC * 2;
    for (int j = t; j < n; j += 256) {
        float v = g_cval[base + j];
        int  id = g_cidx[base + j];
        if (v > v0)      { v1 = v0; i1 = i0; v0 = v; i0 = id; }
        else if (v > v1) { v1 = v;  i1 = id; }
    }
    sv0[t] = v0; sv1[t] = v1; si0[t] = i0; si1[t] = i1;
    __syncthreads();
    for (int s = 128; s > 0; s >>= 1) {
        if (t < s) {
            float bv0 = sv0[t + s], bv1 = sv1[t + s];
            int   bi0 = si0[t + s], bi1 = si1[t + s];
            float a0 = sv0[t], a1 = sv1[t];
            int   c0 = si0[t], c1 = si1[t];
            if (bv0 > a0) {
                a1 = a0; c1 = c0; a0 = bv0; c0 = bi0;
                if (bv1 > a1) { a1 = bv1; c1 = bi1; }
            } else if (bv0 > a1) { a1 = bv0; c1 = bi0; }
            sv0[t] = a0; sv1[t] = a1; si0[t] = c0; si1[t] = c1;
        }
        __syncthreads();
    }
    if (t == 0) { g_sel[b * 2] = si0[0]; g_sel[b * 2 + 1] = si1[0]; }
}

// ---------------- finalize: exact fp32 d_neg + hinge, atomic sum ----------------
__global__ void finalize_kernel(const float* __restrict__ in,
                                const float* __restrict__ tgt,
                                const float* __restrict__ vl,
                                float* __restrict__ out, int Brows) {
    __shared__ float sbuf[5][4];
    int b = blockIdx.x, t = threadIdx.x;      // 128 threads
    int s0 = g_sel[b * 2], s1 = g_sel[b * 2 + 1];
    const float4* ip  = (const float4*)(in  + (size_t)b  * D);
    const float4* tp  = (const float4*)(tgt + (size_t)b  * D);
    const float4* v0p = (const float4*)(vl  + (size_t)s0 * D);
    const float4* v1p = (const float4*)(vl  + (size_t)s1 * D);
    float4 iv = ip[t], tv = tp[t], a = v0p[t], c = v1p[t];

    float ii  = iv.x*iv.x + iv.y*iv.y + iv.z*iv.z + iv.w*iv.w;
    float ia  = iv.x*a.x  + iv.y*a.y  + iv.z*a.z  + iv.w*a.w;
    float aa  = a.x*a.x   + a.y*a.y   + a.z*a.z   + a.w*a.w;
    float ic  = iv.x*c.x  + iv.y*c.y  + iv.z*c.z  + iv.w*c.w;
    float cc  = c.x*c.x   + c.y*c.y   + c.z*c.z   + c.w*c.w;
    int eq = (a.x == tv.x) && (a.y == tv.y) && (a.z == tv.z) && (a.w == tv.w);

    ii = warpSum(ii); ia = warpSum(ia); aa = warpSum(aa);
    ic = warpSum(ic); cc = warpSum(cc);
    int w = t >> 5, l = t & 31;
    if (l == 0) { sbuf[0][w]=ii; sbuf[1][w]=ia; sbuf[2][w]=aa; sbuf[3][w]=ic; sbuf[4][w]=cc; }
    int eq_all = __syncthreads_and(eq);
    if (t == 0) {
        float S[5];
#pragma unroll
        for (int q = 0; q < 5; q++) S[q] = sbuf[q][0]+sbuf[q][1]+sbuf[q][2]+sbuf[q][3];
        float ni = fmaxf(sqrtf(S[0]), EPS);
        float dotv, nn2;
        if (eq_all) { dotv = S[3]; nn2 = S[4]; }
        else        { dotv = S[1]; nn2 = S[2]; }
        float nv  = fmaxf(sqrtf(nn2), EPS);
        float sim = dotv / (ni * nv);
        float dneg = sqrtf(fmaxf(2.0f * (1.0f - sim), 1e-12f));
        float margin = 0.5f + g_dpos[b] - dneg;           // GAMMA + d_pos - d_neg
        float h = 2.0f * fmaxf(margin, 0.0f) / (float)Brows;  // RANK * hinge / B
        if (h != 0.0f) atomicAdd(out, h);
        else           atomicAdd(out, 0.0f);              // keep work uniform
    }
}

__global__ void zero_out_kernel(float* out, int n) {
    int i = blockIdx.x * blockDim.x + threadIdx.x;
    if (i < n) out[i] = 0.0f;
}

extern "C" void kernel_launch(void* const* d_in, const int* in_sizes, int n_in,
                              void* d_out, int out_size) {
    const float* in  = (const float*)d_in[0];
    const float* tgt = (const float*)d_in[1];
    const float* vl  = (const float*)d_in[2];
    float* out = (float*)d_out;

    int Brows = in_sizes[0] / D;      // 4096
    int V     = in_sizes[2] / D;      // 50000
    int NC    = (V + BN - 1) / BN;    // 391

    zero_out_kernel<<<(out_size + 127) / 128, 128>>>(out, out_size);
    prep_input_kernel<<<Brows, 128>>>(in, tgt);
    prep_vec_kernel<<<V, 128>>>(vl, V);
    dim3 ggrid(NC, Brows / BM);
    gemm_topk_kernel<<<ggrid, 256>>>(V, NC);
    reduce_topk_kernel<<<Brows, 256>>>(NC);
    finalize_kernel<<<Brows, 128>>>(in, tgt, vl, out, Brows);
}

// round 7
// speedup vs baseline: 6.8687x; 6.8687x over previous
#include <cuda_runtime.h>
#include <cuda_bf16.h>
#include <cstdint>
#include <math.h>

// Fixed shapes: B=4096, D=512, V=50000
#define D      512
#define EPS    1e-8f
#define NEGINF -1e30f
#define BM 128
#define BN 128
#define BK 64
#define MAXB   4096
#define MAXV   50048
#define MAXNC  400

// -------- device-global scratch (no allocations allowed) --------
__device__ __nv_bfloat16 g_inn_bf16[MAXB * D];   // normalized input, bf16 (4 MB)
__device__ __nv_bfloat16 g_vnn_bf16[MAXV * D];   // normalized veclist, bf16 (~51 MB)
__device__ float g_dpos[MAXB];
__device__ float g_cval[MAXB * MAXNC * 2];
__device__ int   g_cidx[MAXB * MAXNC * 2];
__device__ int   g_sel [MAXB * 2];

__device__ __forceinline__ uint32_t smem_u32(const void* p) {
    uint32_t a;
    asm("{ .reg .u64 t; cvta.to.shared.u64 t, %1; cvt.u32.u64 %0, t; }" : "=r"(a) : "l"(p));
    return a;
}
#define SW128(off) ((off) ^ (((off) >> 3) & 0x70))

#define CP_ASYNC16(dst, src) \
    asm volatile("cp.async.cg.shared.global [%0], [%1], 16;" :: "r"(dst), "l"(src))
#define CP_ASYNC16_ZFILL(dst, src, sz) \
    asm volatile("cp.async.cg.shared.global [%0], [%1], 16, %2;" :: "r"(dst), "l"(src), "r"(sz))
#define CP_COMMIT()  asm volatile("cp.async.commit_group;" ::: "memory")
#define CP_WAIT(n)   asm volatile("cp.async.wait_group %0;" :: "n"(n) : "memory")

#define LDMX4(r0, r1, r2, r3, addr) \
    asm volatile("ldmatrix.sync.aligned.m8n8.x4.shared.b16 {%0,%1,%2,%3}, [%4];" \
                 : "=r"(r0), "=r"(r1), "=r"(r2), "=r"(r3) : "r"(addr))

#define MMA16816(d, a, b0, b1) \
    asm volatile("mma.sync.aligned.m16n8k16.row.col.f32.bf16.bf16.f32 " \
                 "{%0,%1,%2,%3}, {%4,%5,%6,%7}, {%8,%9}, {%0,%1,%2,%3};" \
                 : "+f"((d)[0]), "+f"((d)[1]), "+f"((d)[2]), "+f"((d)[3]) \
                 : "r"((a)[0]), "r"((a)[1]), "r"((a)[2]), "r"((a)[3]), \
                   "r"(b0), "r"(b1))

__device__ __forceinline__ float warpSum(float v) {
#pragma unroll
    for (int o = 16; o > 0; o >>= 1) v += __shfl_down_sync(0xffffffffu, v, o);
    return v;
}

// ---------------- prep: normalize input rows -> bf16, compute d_pos ----------------
__global__ void prep_input_kernel(const float* __restrict__ in,
                                  const float* __restrict__ tgt) {
    __shared__ float sbuf[3][4];
    int b = blockIdx.x, t = threadIdx.x;  // 128 threads
    const float4* ip = (const float4*)(in  + (size_t)b * D);
    const float4* tp = (const float4*)(tgt + (size_t)b * D);
    float4 iv = ip[t], tv = tp[t];
    float ii = iv.x*iv.x + iv.y*iv.y + iv.z*iv.z + iv.w*iv.w;
    float tt = tv.x*tv.x + tv.y*tv.y + tv.z*tv.z + tv.w*tv.w;
    float it = iv.x*tv.x + iv.y*tv.y + iv.z*tv.z + iv.w*tv.w;
    ii = warpSum(ii); tt = warpSum(tt); it = warpSum(it);
    int w = t >> 5, l = t & 31;
    if (l == 0) { sbuf[0][w] = ii; sbuf[1][w] = tt; sbuf[2][w] = it; }
    __syncthreads();
    float s_ii = sbuf[0][0]+sbuf[0][1]+sbuf[0][2]+sbuf[0][3];
    float s_tt = sbuf[1][0]+sbuf[1][1]+sbuf[1][2]+sbuf[1][3];
    float s_it = sbuf[2][0]+sbuf[2][1]+sbuf[2][2]+sbuf[2][3];
    float ni = fmaxf(sqrtf(s_ii), EPS);
    float inv = 1.0f / ni;
    __nv_bfloat162* op = (__nv_bfloat162*)(g_inn_bf16 + (size_t)b * D);
    op[t*2]   = __floats2bfloat162_rn(iv.x*inv, iv.y*inv);
    op[t*2+1] = __floats2bfloat162_rn(iv.z*inv, iv.w*inv);
    if (t == 0) {
        float nt  = fmaxf(sqrtf(s_tt), EPS);
        float sim = s_it / (ni * nt);
        g_dpos[b] = sqrtf(fmaxf(2.0f * (1.0f - sim), 1e-12f));
    }
}

// ---------------- prep: normalize veclist rows -> bf16 ----------------
__global__ void prep_vec_kernel(const float* __restrict__ vl, int V) {
    __shared__ float sbuf[4];
    int v = blockIdx.x;
    if (v >= V) return;
    int t = threadIdx.x;  // 128 threads
    const float4* vp = (const float4*)(vl + (size_t)v * D);
    float4 x = vp[t];
    float nn = x.x*x.x + x.y*x.y + x.z*x.z + x.w*x.w;
    nn = warpSum(nn);
    int w = t >> 5, l = t & 31;
    if (l == 0) sbuf[w] = nn;
    __syncthreads();
    float s = sbuf[0]+sbuf[1]+sbuf[2]+sbuf[3];
    float inv = 1.0f / fmaxf(sqrtf(s), EPS);
    __nv_bfloat162* op = (__nv_bfloat162*)(g_vnn_bf16 + (size_t)v * D);
    op[t*2]   = __floats2bfloat162_rn(x.x*inv, x.y*inv);
    op[t*2+1] = __floats2bfloat162_rn(x.z*inv, x.w*inv);
}

// ---------------- HMMA GEMM + fused per-tile top-2 ----------------
struct Cand { float v0, v1; int i0, i1; };

// dynamic SMEM layout (64 KB):
//   A bufs: 2 x 16 KB at 0, 16384      (128 rows x 64 bf16, SW128)
//   B bufs: 2 x 16 KB at 32768, 49152  (128 rows x 64 bf16, SW128)
//   Cand table (32 KB) aliases A bufs after the mainloop.
#define SMEM_BYTES 65536
#define TILE_B     16384

__global__ void __launch_bounds__(256, 2)
gemm_hmma_kernel(int V, int NC) {
    extern __shared__ __align__(1024) char smem[];
    const uint32_t sb = smem_u32(smem);

    const int tid = threadIdx.x;
    const int w   = tid >> 5, l = tid & 31;
    const int wm  = w & 1;          // M half: rows wm*64 .. +63
    const int wn  = w >> 1;         // N quarter: cols wn*32 .. +31
    const int bx  = blockIdx.x, by = blockIdx.y;
    const int m0  = by * BM, n0 = bx * BN;

    // ---- per-thread cp.async source/dest precompute ----
    // 1024 16B-units per tile, 4 per thread: row = e/8, colu = e%8
    const int erow = tid >> 1;            // rows handled: tid/2 (+64 per i>=2)... use e scheme below

    float acc[4][4][4];
#pragma unroll
    for (int i = 0; i < 4; i++)
#pragma unroll
        for (int j = 0; j < 4; j++)
#pragma unroll
            for (int q = 0; q < 4; q++) acc[i][j][q] = 0.0f;

    // issue A+B chunk ck into buffer buf
    auto load_chunk = [&](int ck, int buf) {
#pragma unroll
        for (int i = 0; i < 4; i++) {
            int e = tid + i * 256;
            int row = e >> 3, cu = e & 7;
            uint32_t so = SW128((uint32_t)(row * 128 + cu * 16));
            const char* srcA = (const char*)g_inn_bf16
                             + (size_t)(m0 + row) * (D * 2) + ck * 128 + cu * 16;
            CP_ASYNC16(sb + buf * TILE_B + so, srcA);
        }
#pragma unroll
        for (int i = 0; i < 4; i++) {
            int e = tid + i * 256;
            int row = e >> 3, cu = e & 7;
            int vr = n0 + row;
            uint32_t so = SW128((uint32_t)(row * 128 + cu * 16));
            int vrc = vr < V ? vr : (V - 1);
            const char* srcB = (const char*)g_vnn_bf16
                             + (size_t)vrc * (D * 2) + ck * 128 + cu * 16;
            uint32_t sz = (vr < V) ? 16u : 0u;
            CP_ASYNC16_ZFILL(sb + 32768 + buf * TILE_B + so, srcB, sz);
        }
        CP_COMMIT();
    };

    load_chunk(0, 0);

    // ---- precompute ldmatrix base offsets (lane-dependent) ----
    // A: row = wm*64 + mt*16 + (l%16), kbyte = ks*32 + (l/16)*16
    // B: row = wn*32 + np*16 + (l%16), same kbyte
    const int lrow16 = l & 15, khalf = (l >> 4) * 16;

#pragma unroll 1
    for (int ck = 0; ck < 8; ck++) {
        const int buf = ck & 1;
        if (ck < 7) { load_chunk(ck + 1, buf ^ 1); CP_WAIT(1); }
        else        { CP_WAIT(0); }
        __syncthreads();

        const uint32_t aBase = sb + buf * TILE_B;
        const uint32_t bBase = sb + 32768 + buf * TILE_B;

#pragma unroll
        for (int ks = 0; ks < 4; ks++) {
            uint32_t af[4][4], bf[2][4];
#pragma unroll
            for (int mt = 0; mt < 4; mt++) {
                int row = wm * 64 + mt * 16 + lrow16;
                uint32_t off = SW128((uint32_t)(row * 128 + ks * 32 + khalf));
                LDMX4(af[mt][0], af[mt][1], af[mt][2], af[mt][3], aBase + off);
            }
#pragma unroll
            for (int np = 0; np < 2; np++) {
                int row = wn * 32 + np * 16 + lrow16;
                uint32_t off = SW128((uint32_t)(row * 128 + ks * 32 + khalf));
                LDMX4(bf[np][0], bf[np][1], bf[np][2], bf[np][3], bBase + off);
            }
#pragma unroll
            for (int mt = 0; mt < 4; mt++)
#pragma unroll
                for (int nt = 0; nt < 4; nt++) {
                    int np = nt >> 1, hi = nt & 1;
                    MMA16816(acc[mt][nt], af[mt], bf[np][hi], bf[np][hi + 2]);
                }
        }
        __syncthreads();
    }

    // ---- epilogue: per-thread top-2, Cand merge (aliases A bufs) ----
    Cand (*sc)[16] = reinterpret_cast<Cand (*)[16]>(smem);
    const int qidx = wn * 4 + (l & 3);

#pragma unroll
    for (int mt = 0; mt < 4; mt++) {
#pragma unroll
        for (int h = 0; h < 2; h++) {
            int lrow = wm * 64 + mt * 16 + h * 8 + (l >> 2);
            float v0 = NEGINF, v1 = NEGINF; int i0 = -1, i1 = -1;
#pragma unroll
            for (int nt = 0; nt < 4; nt++) {
#pragma unroll
                for (int e = 0; e < 2; e++) {
                    int col = n0 + wn * 32 + nt * 8 + 2 * (l & 3) + e;
                    float v = (col < V) ? acc[mt][nt][h * 2 + e] : NEGINF;
                    if (v > v0)      { v1 = v0; i1 = i0; v0 = v; i0 = col; }
                    else if (v > v1) { v1 = v;  i1 = col; }
                }
            }
            Cand c; c.v0 = v0; c.v1 = v1; c.i0 = i0; c.i1 = i1;
            sc[lrow][qidx] = c;
        }
    }
    __syncthreads();

    if (tid < BM) {
        float v0 = NEGINF, v1 = NEGINF; int i0 = -1, i1 = -1;
#pragma unroll 4
        for (int q = 0; q < 16; q++) {
            Cand c = sc[tid][q];
            if (c.v0 > v0) {
                v1 = v0; i1 = i0; v0 = c.v0; i0 = c.i0;
                if (c.v1 > v1) { v1 = c.v1; i1 = c.i1; }
            } else if (c.v0 > v1) { v1 = c.v0; i1 = c.i0; }
        }
        size_t base = ((size_t)(m0 + tid) * NC + bx) * 2;
        g_cval[base]     = v0; g_cidx[base]     = i0;
        g_cval[base + 1] = v1; g_cidx[base + 1] = i1;
    }
}

// ---------------- merge chunk candidates -> global top-2 per row ----------------
__global__ void reduce_topk_kernel(int NC) {
    __shared__ float sv0[256], sv1[256];
    __shared__ int   si0[256], si1[256];
    int b = blockIdx.x, t = threadIdx.x;
    int n = NC * 2;
    float v0 = NEGINF, v1 = NEGINF; int i0 = -1, i1 = -1;
    size_t base = (size_t)b * NC * 2;
    for (int j = t; j < n; j += 256) {
        float v = g_cval[base + j];
        int  id = g_cidx[base + j];
        if (v > v0)      { v1 = v0; i1 = i0; v0 = v; i0 = id; }
        else if (v > v1) { v1 = v;  i1 = id; }
    }
    sv0[t] = v0; sv1[t] = v1; si0[t] = i0; si1[t] = i1;
    __syncthreads();
    for (int s = 128; s > 0; s >>= 1) {
        if (t < s) {
            float bv0 = sv0[t+s], bv1 = sv1[t+s];
            int   bi0 = si0[t+s], bi1 = si1[t+s];
            float a0 = sv0[t], a1 = sv1[t];
            int   c0 = si0[t], c1 = si1[t];
            if (bv0 > a0) {
                a1 = a0; c1 = c0; a0 = bv0; c0 = bi0;
                if (bv1 > a1) { a1 = bv1; c1 = bi1; }
            } else if (bv0 > a1) { a1 = bv0; c1 = bi0; }
            sv0[t] = a0; sv1[t] = a1; si0[t] = c0; si1[t] = c1;
        }
        __syncthreads();
    }
    if (t == 0) { g_sel[b*2] = si0[0]; g_sel[b*2+1] = si1[0]; }
}

// ---------------- finalize: exact fp32 d_neg + hinge, atomic sum ----------------
__global__ void finalize_kernel(const float* __restrict__ in,
                                const float* __restrict__ tgt,
                                const float* __restrict__ vl,
                                float* __restrict__ out, int Brows) {
    __shared__ float sbuf[5][4];
    int b = blockIdx.x, t = threadIdx.x;   // 128 threads
    int s0 = g_sel[b*2], s1 = g_sel[b*2+1];
    const float4* ip  = (const float4*)(in  + (size_t)b  * D);
    const float4* tp  = (const float4*)(tgt + (size_t)b  * D);
    const float4* v0p = (const float4*)(vl  + (size_t)s0 * D);
    const float4* v1p = (const float4*)(vl  + (size_t)s1 * D);
    float4 iv = ip[t], tv = tp[t], a = v0p[t], c = v1p[t];

    float ii = iv.x*iv.x + iv.y*iv.y + iv.z*iv.z + iv.w*iv.w;
    float ia = iv.x*a.x  + iv.y*a.y  + iv.z*a.z  + iv.w*a.w;
    float aa = a.x*a.x   + a.y*a.y   + a.z*a.z   + a.w*a.w;
    float ic = iv.x*c.x  + iv.y*c.y  + iv.z*c.z  + iv.w*c.w;
    float cc = c.x*c.x   + c.y*c.y   + c.z*c.z   + c.w*c.w;
    int eq = (a.x == tv.x) && (a.y == tv.y) && (a.z == tv.z) && (a.w == tv.w);

    ii = warpSum(ii); ia = warpSum(ia); aa = warpSum(aa);
    ic = warpSum(ic); cc = warpSum(cc);
    int w = t >> 5, l = t & 31;
    if (l == 0) { sbuf[0][w]=ii; sbuf[1][w]=ia; sbuf[2][w]=aa; sbuf[3][w]=ic; sbuf[4][w]=cc; }
    int eq_all = __syncthreads_and(eq);
    if (t == 0) {
        float S[5];
#pragma unroll
        for (int qq = 0; qq < 5; qq++) S[qq] = sbuf[qq][0]+sbuf[qq][1]+sbuf[qq][2]+sbuf[qq][3];
        float ni = fmaxf(sqrtf(S[0]), EPS);
        float dotv, nn2;
        if (eq_all) { dotv = S[3]; nn2 = S[4]; }
        else        { dotv = S[1]; nn2 = S[2]; }
        float nv  = fmaxf(sqrtf(nn2), EPS);
        float sim = dotv / (ni * nv);
        float dneg = sqrtf(fmaxf(2.0f * (1.0f - sim), 1e-12f));
        float margin = 0.5f + g_dpos[b] - dneg;               // GAMMA + d_pos - d_neg
        float h = 2.0f * fmaxf(margin, 0.0f) / (float)Brows;  // RANK * hinge / B
        if (h != 0.0f) atomicAdd(out, h);
        else           atomicAdd(out, 0.0f);
    }
}

__global__ void zero_out_kernel(float* out, int n) {
    int i = blockIdx.x * blockDim.x + threadIdx.x;
    if (i < n) out[i] = 0.0f;
}

extern "C" void kernel_launch(void* const* d_in, const int* in_sizes, int n_in,
                              void* d_out, int out_size) {
    const float* in  = (const float*)d_in[0];
    const float* tgt = (const float*)d_in[1];
    const float* vl  = (const float*)d_in[2];
    float* out = (float*)d_out;

    int Brows = in_sizes[0] / D;      // 4096
    int V     = in_sizes[2] / D;      // 50000
    int NC    = (V + BN - 1) / BN;    // 391

    zero_out_kernel<<<(out_size + 127) / 128, 128>>>(out, out_size);
    prep_input_kernel<<<Brows, 128>>>(in, tgt);
    prep_vec_kernel<<<V, 128>>>(vl, V);

    static int smem_set = 0;
    if (!smem_set) {
        cudaFuncSetAttribute(gemm_hmma_kernel,
                             cudaFuncAttributeMaxDynamicSharedMemorySize, SMEM_BYTES);
        smem_set = 1;
    }
    dim3 ggrid(NC, Brows / BM);
    gemm_hmma_kernel<<<ggrid, 256, SMEM_BYTES>>>(V, NC);

    reduce_topk_kernel<<<Brows, 256>>>(NC);
    finalize_kernel<<<Brows, 128>>>(in, tgt, vl, out, Brows);
}

// round 8
// speedup vs baseline: 7.2468x; 1.0551x over previous
#include <cuda_runtime.h>
#include <cuda_bf16.h>
#include <cstdint>
#include <math.h>

// Fixed shapes: B=4096, D=512, V=50000
#define D      512
#define EPS    1e-8f
#define NEGINF -1e30f
#define BM 128
#define BN 128
#define BK 64
#define MAXB   4096
#define MAXV   50048
#define MAXNC  400

// -------- device-global scratch (no allocations allowed) --------
__device__ __nv_bfloat16 g_inn_bf16[MAXB * D];   // normalized input, bf16 (4 MB)
__device__ __nv_bfloat16 g_vnn_bf16[MAXV * D];   // normalized veclist, bf16 (~51 MB)
__device__ float g_dpos[MAXB];
__device__ float g_cval[MAXB * MAXNC * 2];
__device__ int   g_cidx[MAXB * MAXNC * 2];
__device__ int   g_sel [MAXB * 2];

__device__ __forceinline__ uint32_t smem_u32(const void* p) {
    uint32_t a;
    asm("{ .reg .u64 t; cvta.to.shared.u64 t, %1; cvt.u32.u64 %0, t; }" : "=r"(a) : "l"(p));
    return a;
}
#define SW128(off) ((off) ^ (((off) >> 3) & 0x70))

#define CP_ASYNC16(dst, src) \
    asm volatile("cp.async.cg.shared.global [%0], [%1], 16;" :: "r"(dst), "l"(src))
#define CP_ASYNC16_ZFILL(dst, src, sz) \
    asm volatile("cp.async.cg.shared.global [%0], [%1], 16, %2;" :: "r"(dst), "l"(src), "r"(sz))
#define CP_COMMIT()  asm volatile("cp.async.commit_group;" ::: "memory")
#define CP_WAIT(n)   asm volatile("cp.async.wait_group %0;" :: "n"(n) : "memory")

#define LDMX4(r0, r1, r2, r3, addr) \
    asm volatile("ldmatrix.sync.aligned.m8n8.x4.shared.b16 {%0,%1,%2,%3}, [%4];" \
                 : "=r"(r0), "=r"(r1), "=r"(r2), "=r"(r3) : "r"(addr))

#define MMA16816(d, a, b0, b1) \
    asm volatile("mma.sync.aligned.m16n8k16.row.col.f32.bf16.bf16.f32 " \
                 "{%0,%1,%2,%3}, {%4,%5,%6,%7}, {%8,%9}, {%0,%1,%2,%3};" \
                 : "+f"((d)[0]), "+f"((d)[1]), "+f"((d)[2]), "+f"((d)[3]) \
                 : "r"((a)[0]), "r"((a)[1]), "r"((a)[2]), "r"((a)[3]), \
                   "r"(b0), "r"(b1))

__device__ __forceinline__ float warpSum(float v) {
#pragma unroll
    for (int o = 16; o > 0; o >>= 1) v += __shfl_down_sync(0xffffffffu, v, o);
    return v;
}

// ---------------- prep: normalize input rows -> bf16, compute d_pos ----------------
__global__ void prep_input_kernel(const float* __restrict__ in,
                                  const float* __restrict__ tgt) {
    __shared__ float sbuf[3][4];
    int b = blockIdx.x, t = threadIdx.x;  // 128 threads
    const float4* ip = (const float4*)(in  + (size_t)b * D);
    const float4* tp = (const float4*)(tgt + (size_t)b * D);
    float4 iv = ip[t], tv = tp[t];
    float ii = iv.x*iv.x + iv.y*iv.y + iv.z*iv.z + iv.w*iv.w;
    float tt = tv.x*tv.x + tv.y*tv.y + tv.z*tv.z + tv.w*tv.w;
    float it = iv.x*tv.x + iv.y*tv.y + iv.z*tv.z + iv.w*tv.w;
    ii = warpSum(ii); tt = warpSum(tt); it = warpSum(it);
    int w = t >> 5, l = t & 31;
    if (l == 0) { sbuf[0][w] = ii; sbuf[1][w] = tt; sbuf[2][w] = it; }
    __syncthreads();
    float s_ii = sbuf[0][0]+sbuf[0][1]+sbuf[0][2]+sbuf[0][3];
    float s_tt = sbuf[1][0]+sbuf[1][1]+sbuf[1][2]+sbuf[1][3];
    float s_it = sbuf[2][0]+sbuf[2][1]+sbuf[2][2]+sbuf[2][3];
    float ni = fmaxf(sqrtf(s_ii), EPS);
    float inv = 1.0f / ni;
    __nv_bfloat162* op = (__nv_bfloat162*)(g_inn_bf16 + (size_t)b * D);
    op[t*2]   = __floats2bfloat162_rn(iv.x*inv, iv.y*inv);
    op[t*2+1] = __floats2bfloat162_rn(iv.z*inv, iv.w*inv);
    if (t == 0) {
        float nt  = fmaxf(sqrtf(s_tt), EPS);
        float sim = s_it / (ni * nt);
        g_dpos[b] = sqrtf(fmaxf(2.0f * (1.0f - sim), 1e-12f));
    }
}

// ---------------- prep: normalize veclist rows -> bf16 ----------------
__global__ void prep_vec_kernel(const float* __restrict__ vl, int V) {
    __shared__ float sbuf[4];
    int v = blockIdx.x;
    if (v >= V) return;
    int t = threadIdx.x;  // 128 threads
    const float4* vp = (const float4*)(vl + (size_t)v * D);
    float4 x = vp[t];
    float nn = x.x*x.x + x.y*x.y + x.z*x.z + x.w*x.w;
    nn = warpSum(nn);
    int w = t >> 5, l = t & 31;
    if (l == 0) sbuf[w] = nn;
    __syncthreads();
    float s = sbuf[0]+sbuf[1]+sbuf[2]+sbuf[3];
    float inv = 1.0f / fmaxf(sqrtf(s), EPS);
    __nv_bfloat162* op = (__nv_bfloat162*)(g_vnn_bf16 + (size_t)v * D);
    op[t*2]   = __floats2bfloat162_rn(x.x*inv, x.y*inv);
    op[t*2+1] = __floats2bfloat162_rn(x.z*inv, x.w*inv);
}

// ---------------- HMMA GEMM + fused per-tile top-2 ----------------
struct Cand { float v0, v1; int i0, i1; };

// dynamic SMEM layout (64 KB):
//   A bufs: 2 x 16 KB at 0, 16384      (128 rows x 64 bf16, SW128)
//   B bufs: 2 x 16 KB at 32768, 49152  (128 rows x 64 bf16, SW128)
//   Cand table sc[16][128] (32 KB) aliases A bufs after the mainloop.
#define SMEM_BYTES 65536
#define TILE_B     16384

// per-thread top-2 over this thread's fragment columns; MASK = tail tile only
template <bool MASK>
__device__ __forceinline__ void epilogue_topk(const float acc[4][4][4],
                                              Cand (*sc)[128],
                                              int wm, int wn, int l,
                                              int n0, int V, int qidx) {
#pragma unroll
    for (int mt = 0; mt < 4; mt++) {
#pragma unroll
        for (int h = 0; h < 2; h++) {
            int lrow = wm * 64 + mt * 16 + h * 8 + (l >> 2);
            float v0 = NEGINF, v1 = NEGINF; int i0 = -1, i1 = -1;
#pragma unroll
            for (int nt = 0; nt < 4; nt++) {
#pragma unroll
                for (int e = 0; e < 2; e++) {
                    int col = n0 + wn * 32 + nt * 8 + 2 * (l & 3) + e;
                    float v = acc[mt][nt][h * 2 + e];
                    if (MASK && col >= V) v = NEGINF;
                    if (v > v0)      { v1 = v0; i1 = i0; v0 = v; i0 = col; }
                    else if (v > v1) { v1 = v;  i1 = col; }
                }
            }
            Cand c; c.v0 = v0; c.v1 = v1; c.i0 = i0; c.i1 = i1;
            sc[qidx][lrow] = c;
        }
    }
}

__global__ void __launch_bounds__(256, 2)
gemm_hmma_kernel(int V, int NC) {
    extern __shared__ __align__(1024) char smem[];
    const uint32_t sb = smem_u32(smem);

    const int tid = threadIdx.x;
    const int w   = tid >> 5, l = tid & 31;
    const int wm  = w & 1;          // M half: rows wm*64 .. +63
    const int wn  = w >> 1;         // N quarter: cols wn*32 .. +31
    const int bx  = blockIdx.x, by = blockIdx.y;
    const int m0  = by * BM, n0 = bx * BN;

    float acc[4][4][4];
#pragma unroll
    for (int i = 0; i < 4; i++)
#pragma unroll
        for (int j = 0; j < 4; j++)
#pragma unroll
            for (int q = 0; q < 4; q++) acc[i][j][q] = 0.0f;

    // ---- hoisted cp.async addressing: 4 (row, colu) slots per thread ----
    const char* srcA[4];
    const char* srcB[4];
    uint32_t    dofs[4];   // swizzled dest offset within a 16 KB tile buffer
    uint32_t    szB[4];
#pragma unroll
    for (int i = 0; i < 4; i++) {
        int e = tid + i * 256;
        int row = e >> 3, cu = e & 7;
        dofs[i] = SW128((uint32_t)(row * 128 + cu * 16));
        srcA[i] = (const char*)g_inn_bf16 + (size_t)(m0 + row) * (D * 2) + cu * 16;
        int vr = n0 + row;
        int vrc = vr < V ? vr : (V - 1);
        srcB[i] = (const char*)g_vnn_bf16 + (size_t)vrc * (D * 2) + cu * 16;
        szB[i]  = (vr < V) ? 16u : 0u;
    }

    auto load_chunk = [&](int buf) {
        const uint32_t da = sb + buf * TILE_B;
        const uint32_t db = sb + 32768 + buf * TILE_B;
#pragma unroll
        for (int i = 0; i < 4; i++) CP_ASYNC16(da + dofs[i], srcA[i]);
#pragma unroll
        for (int i = 0; i < 4; i++) CP_ASYNC16_ZFILL(db + dofs[i], srcB[i], szB[i]);
        CP_COMMIT();
#pragma unroll
        for (int i = 0; i < 4; i++) { srcA[i] += 128; srcB[i] += 128; }
    };

    load_chunk(0);

    // ---- hoisted ldmatrix addressing ----
    // off(row, ks) = row*128 + ((ks*32 + khalf) ^ ((row&7)<<4)); row&7 == lrow16&7
    const int lrow16 = l & 15, khalf = (l >> 4) * 16;
    const uint32_t xorv = (uint32_t)((lrow16 & 7) << 4);
    uint32_t koff[4];
#pragma unroll
    for (int ks = 0; ks < 4; ks++) koff[ks] = ((uint32_t)(ks * 32 + khalf)) ^ xorv;
    uint32_t aRow[4], bRow[2];
#pragma unroll
    for (int mt = 0; mt < 4; mt++) aRow[mt] = (uint32_t)((wm * 64 + mt * 16 + lrow16) * 128);
#pragma unroll
    for (int np = 0; np < 2; np++) bRow[np] = (uint32_t)((wn * 32 + np * 16 + lrow16) * 128);

#pragma unroll 1
    for (int ck = 0; ck < 8; ck++) {
        const int buf = ck & 1;
        if (ck < 7) { load_chunk(buf ^ 1); CP_WAIT(1); }
        else        { CP_WAIT(0); }
        __syncthreads();

        const uint32_t aBase = sb + buf * TILE_B;
        const uint32_t bBase = sb + 32768 + buf * TILE_B;

#pragma unroll
        for (int ks = 0; ks < 4; ks++) {
            uint32_t af[4][4], bf[2][4];
#pragma unroll
            for (int mt = 0; mt < 4; mt++)
                LDMX4(af[mt][0], af[mt][1], af[mt][2], af[mt][3],
                      aBase + aRow[mt] + koff[ks]);
#pragma unroll
            for (int np = 0; np < 2; np++)
                LDMX4(bf[np][0], bf[np][1], bf[np][2], bf[np][3],
                      bBase + bRow[np] + koff[ks]);
            // after the final smem reads of this buffer, release it so next
            // chunk's cp.async (issued right after the barrier) can overwrite
            // while the remaining MMAs (register-only) still execute.
            if (ks == 3) __syncthreads();
#pragma unroll
            for (int mt = 0; mt < 4; mt++)
#pragma unroll
                for (int nt = 0; nt < 4; nt++) {
                    int np = nt >> 1, hi = nt & 1;
                    MMA16816(acc[mt][nt], af[mt], bf[np][hi], bf[np][hi + 2]);
                }
        }
    }

    // ---- epilogue: transposed Cand table sc[q][row] (16 B row pitch) ----
    Cand (*sc)[128] = reinterpret_cast<Cand (*)[128]>(smem);
    const int qidx = wn * 4 + (l & 3);

    if (n0 + BN <= V) epilogue_topk<false>(acc, sc, wm, wn, l, n0, V, qidx);
    else              epilogue_topk<true >(acc, sc, wm, wn, l, n0, V, qidx);
    __syncthreads();

    if (tid < BM) {
        float v0 = NEGINF, v1 = NEGINF; int i0 = -1, i1 = -1;
#pragma unroll 4
        for (int q = 0; q < 16; q++) {
            Cand c = sc[q][tid];            // lanes consecutive 16 B: conflict-free
            if (c.v0 > v0) {
                v1 = v0; i1 = i0; v0 = c.v0; i0 = c.i0;
                if (c.v1 > v1) { v1 = c.v1; i1 = c.i1; }
            } else if (c.v0 > v1) { v1 = c.v0; i1 = c.i0; }
        }
        size_t base = ((size_t)(m0 + tid) * NC + bx) * 2;
        g_cval[base]     = v0; g_cidx[base]     = i0;
        g_cval[base + 1] = v1; g_cidx[base + 1] = i1;
    }
}

// ---------------- merge chunk candidates -> global top-2 per row ----------------
__global__ void reduce_topk_kernel(int NC) {
    __shared__ float sv0[256], sv1[256];
    __shared__ int   si0[256], si1[256];
    int b = blockIdx.x, t = threadIdx.x;
    int n = NC * 2;
    float v0 = NEGINF, v1 = NEGINF; int i0 = -1, i1 = -1;
    size_t base = (size_t)b * NC * 2;
    for (int j = t; j < n; j += 256) {
        float v = g_cval[base + j];
        int  id = g_cidx[base + j];
        if (v > v0)      { v1 = v0; i1 = i0; v0 = v; i0 = id; }
        else if (v > v1) { v1 = v;  i1 = id; }
    }
    sv0[t] = v0; sv1[t] = v1; si0[t] = i0; si1[t] = i1;
    __syncthreads();
    for (int s = 128; s > 0; s >>= 1) {
        if (t < s) {
            float bv0 = sv0[t+s], bv1 = sv1[t+s];
            int   bi0 = si0[t+s], bi1 = si1[t+s];
            float a0 = sv0[t], a1 = sv1[t];
            int   c0 = si0[t], c1 = si1[t];
            if (bv0 > a0) {
                a1 = a0; c1 = c0; a0 = bv0; c0 = bi0;
                if (bv1 > a1) { a1 = bv1; c1 = bi1; }
            } else if (bv0 > a1) { a1 = bv0; c1 = bi0; }
            sv0[t] = a0; sv1[t] = a1; si0[t] = c0; si1[t] = c1;
        }
        __syncthreads();
    }
    if (t == 0) { g_sel[b*2] = si0[0]; g_sel[b*2+1] = si1[0]; }
}

// ---------------- finalize: exact fp32 d_neg + hinge, atomic sum ----------------
__global__ void finalize_kernel(const float* __restrict__ in,
                                const float* __restrict__ tgt,
                                const float* __restrict__ vl,
                                float* __restrict__ out, int Brows) {
    __shared__ float sbuf[5][4];
    int b = blockIdx.x, t = threadIdx.x;   // 128 threads
    int s0 = g_sel[b*2], s1 = g_sel[b*2+1];
    const float4* ip  = (const float4*)(in  + (size_t)b  * D);
    const float4* tp  = (const float4*)(tgt + (size_t)b  * D);
    const float4* v0p = (const float4*)(vl  + (size_t)s0 * D);
    const float4* v1p = (const float4*)(vl  + (size_t)s1 * D);
    float4 iv = ip[t], tv = tp[t], a = v0p[t], c = v1p[t];

    float ii = iv.x*iv.x + iv.y*iv.y + iv.z*iv.z + iv.w*iv.w;
    float ia = iv.x*a.x  + iv.y*a.y  + iv.z*a.z  + iv.w*a.w;
    float aa = a.x*a.x   + a.y*a.y   + a.z*a.z   + a.w*a.w;
    float ic = iv.x*c.x  + iv.y*c.y  + iv.z*c.z  + iv.w*c.w;
    float cc = c.x*c.x   + c.y*c.y   + c.z*c.z   + c.w*c.w;
    int eq = (a.x == tv.x) && (a.y == tv.y) && (a.z == tv.z) && (a.w == tv.w);

    ii = warpSum(ii); ia = warpSum(ia); aa = warpSum(aa);
    ic = warpSum(ic); cc = warpSum(cc);
    int w = t >> 5, l = t & 31;
    if (l == 0) { sbuf[0][w]=ii; sbuf[1][w]=ia; sbuf[2][w]=aa; sbuf[3][w]=ic; sbuf[4][w]=cc; }
    int eq_all = __syncthreads_and(eq);
    if (t == 0) {
        float S[5];
#pragma unroll
        for (int qq = 0; qq < 5; qq++) S[qq] = sbuf[qq][0]+sbuf[qq][1]+sbuf[qq][2]+sbuf[qq][3];
        float ni = fmaxf(sqrtf(S[0]), EPS);
        float dotv, nn2;
        if (eq_all) { dotv = S[3]; nn2 = S[4]; }
        else        { dotv = S[1]; nn2 = S[2]; }
        float nv  = fmaxf(sqrtf(nn2), EPS);
        float sim = dotv / (ni * nv);
        float dneg = sqrtf(fmaxf(2.0f * (1.0f - sim), 1e-12f));
        float margin = 0.5f + g_dpos[b] - dneg;               // GAMMA + d_pos - d_neg
        float h = 2.0f * fmaxf(margin, 0.0f) / (float)Brows;  // RANK * hinge / B
        if (h != 0.0f) atomicAdd(out, h);
        else           atomicAdd(out, 0.0f);
    }
}

__global__ void zero_out_kernel(float* out, int n) {
    int i = blockIdx.x * blockDim.x + threadIdx.x;
    if (i < n) out[i] = 0.0f;
}

extern "C" void kernel_launch(void* const* d_in, const int* in_sizes, int n_in,
                              void* d_out, int out_size) {
    const float* in  = (const float*)d_in[0];
    const float* tgt = (const float*)d_in[1];
    const float* vl  = (const float*)d_in[2];
    float* out = (float*)d_out;

    int Brows = in_sizes[0] / D;      // 4096
    int V     = in_sizes[2] / D;      // 50000
    int NC    = (V + BN - 1) / BN;    // 391

    zero_out_kernel<<<(out_size + 127) / 128, 128>>>(out, out_size);
    prep_input_kernel<<<Brows, 128>>>(in, tgt);
    prep_vec_kernel<<<V, 128>>>(vl, V);

    static int smem_set = 0;
    if (!smem_set) {
        cudaFuncSetAttribute(gemm_hmma_kernel,
                             cudaFuncAttributeMaxDynamicSharedMemorySize, SMEM_BYTES);
        smem_set = 1;
    }
    dim3 ggrid(NC, Brows / BM);
    gemm_hmma_kernel<<<ggrid, 256, SMEM_BYTES>>>(V, NC);

    reduce_topk_kernel<<<Brows, 256>>>(NC);
    finalize_kernel<<<Brows, 128>>>(in, tgt, vl, out, Brows);
}

// round 11
// speedup vs baseline: 7.4125x; 1.0229x over previous
#include <cuda_runtime.h>
#include <cuda_bf16.h>
#include <cstdint>
#include <math.h>

// Fixed shapes: B=4096, D=512, V=50000
#define D      512
#define EPS    1e-8f
#define NEGINF -1e30f
#define BM 128
#define BN 128
#define BK 64
#define MAXB   4096
#define MAXV   50048
#define MAXNC  400

// -------- device-global scratch (no allocations allowed) --------
__device__ __nv_bfloat16 g_inn_bf16[MAXB * D];   // normalized input, bf16 (4 MB)
__device__ __nv_bfloat16 g_vnn_bf16[MAXV * D];   // normalized veclist, bf16 (~51 MB)
__device__ float g_dpos[MAXB];
__device__ float g_cval[MAXB * MAXNC * 2];
__device__ int   g_cidx[MAXB * MAXNC * 2];
__device__ int   g_sel [MAXB * 2];

__device__ __forceinline__ uint32_t smem_u32(const void* p) {
    uint32_t a;
    asm("{ .reg .u64 t; cvta.to.shared.u64 t, %1; cvt.u32.u64 %0, t; }" : "=r"(a) : "l"(p));
    return a;
}
#define SW128(off) ((off) ^ (((off) >> 3) & 0x70))

#define CP_ASYNC16(dst, src) \
    asm volatile("cp.async.cg.shared.global [%0], [%1], 16;" :: "r"(dst), "l"(src))
#define CP_ASYNC16_ZFILL(dst, src, sz) \
    asm volatile("cp.async.cg.shared.global [%0], [%1], 16, %2;" :: "r"(dst), "l"(src), "r"(sz))
#define CP_COMMIT()  asm volatile("cp.async.commit_group;" ::: "memory")
#define CP_WAIT(n)   asm volatile("cp.async.wait_group %0;" :: "n"(n) : "memory")

#define LDMX4(r0, r1, r2, r3, addr) \
    asm volatile("ldmatrix.sync.aligned.m8n8.x4.shared.b16 {%0,%1,%2,%3}, [%4];" \
                 : "=r"(r0), "=r"(r1), "=r"(r2), "=r"(r3) : "r"(addr))

#define MMA16816(d, a, b0, b1) \
    asm volatile("mma.sync.aligned.m16n8k16.row.col.f32.bf16.bf16.f32 " \
                 "{%0,%1,%2,%3}, {%4,%5,%6,%7}, {%8,%9}, {%0,%1,%2,%3};" \
                 : "+f"((d)[0]), "+f"((d)[1]), "+f"((d)[2]), "+f"((d)[3]) \
                 : "r"((a)[0]), "r"((a)[1]), "r"((a)[2]), "r"((a)[3]), \
                   "r"(b0), "r"(b1))

__device__ __forceinline__ float warpSum(float v) {
#pragma unroll
    for (int o = 16; o > 0; o >>= 1) v += __shfl_down_sync(0xffffffffu, v, o);
    return v;
}

// ---------------- prep: normalize input rows -> bf16, compute d_pos ----------------
__global__ void prep_input_kernel(const float* __restrict__ in,
                                  const float* __restrict__ tgt) {
    __shared__ float sbuf[3][4];
    int b = blockIdx.x, t = threadIdx.x;  // 128 threads
    const float4* ip = (const float4*)(in  + (size_t)b * D);
    const float4* tp = (const float4*)(tgt + (size_t)b * D);
    float4 iv = ip[t], tv = tp[t];
    float ii = iv.x*iv.x + iv.y*iv.y + iv.z*iv.z + iv.w*iv.w;
    float tt = tv.x*tv.x + tv.y*tv.y + tv.z*tv.z + tv.w*tv.w;
    float it = iv.x*tv.x + iv.y*tv.y + iv.z*tv.z + iv.w*tv.w;
    ii = warpSum(ii); tt = warpSum(tt); it = warpSum(it);
    int w = t >> 5, l = t & 31;
    if (l == 0) { sbuf[0][w] = ii; sbuf[1][w] = tt; sbuf[2][w] = it; }
    __syncthreads();
    float s_ii = sbuf[0][0]+sbuf[0][1]+sbuf[0][2]+sbuf[0][3];
    float s_tt = sbuf[1][0]+sbuf[1][1]+sbuf[1][2]+sbuf[1][3];
    float s_it = sbuf[2][0]+sbuf[2][1]+sbuf[2][2]+sbuf[2][3];
    float ni = fmaxf(sqrtf(s_ii), EPS);
    float inv = 1.0f / ni;
    __nv_bfloat162* op = (__nv_bfloat162*)(g_inn_bf16 + (size_t)b * D);
    op[t*2]   = __floats2bfloat162_rn(iv.x*inv, iv.y*inv);
    op[t*2+1] = __floats2bfloat162_rn(iv.z*inv, iv.w*inv);
    if (t == 0) {
        float nt  = fmaxf(sqrtf(s_tt), EPS);
        float sim = s_it / (ni * nt);
        g_dpos[b] = sqrtf(fmaxf(2.0f * (1.0f - sim), 1e-12f));
    }
}

// ---------------- prep: normalize veclist rows -> bf16 ----------------
__global__ void prep_vec_kernel(const float* __restrict__ vl, int V) {
    __shared__ float sbuf[4];
    int v = blockIdx.x;
    if (v >= V) return;
    int t = threadIdx.x;  // 128 threads
    const float4* vp = (const float4*)(vl + (size_t)v * D);
    float4 x = vp[t];
    float nn = x.x*x.x + x.y*x.y + x.z*x.z + x.w*x.w;
    nn = warpSum(nn);
    int w = t >> 5, l = t & 31;
    if (l == 0) sbuf[w] = nn;
    __syncthreads();
    float s = sbuf[0]+sbuf[1]+sbuf[2]+sbuf[3];
    float inv = 1.0f / fmaxf(sqrtf(s), EPS);
    __nv_bfloat162* op = (__nv_bfloat162*)(g_vnn_bf16 + (size_t)v * D);
    op[t*2]   = __floats2bfloat162_rn(x.x*inv, x.y*inv);
    op[t*2+1] = __floats2bfloat162_rn(x.z*inv, x.w*inv);
}

// ---------------- HMMA GEMM + fused per-tile top-2 ----------------
struct Cand { float v0, v1; int i0, i1; };

// dynamic SMEM layout (64 KB):
//   A bufs: 2 x 16 KB at 0, 16384      (128 rows x 64 bf16, SW128)
//   B bufs: 2 x 16 KB at 32768, 49152  (128 rows x 64 bf16, SW128)
//   Cand table sc[8][128] (16 KB) aliases A bufs after the mainloop.
#define SMEM_BYTES 65536
#define TILE_B     16384

// per-thread top-2 over this thread's fragment columns; MASK = tail tile only
template <bool MASK>
__device__ __forceinline__ void epilogue_topk(const float acc[4][8][4],
                                              Cand (*sc)[128],
                                              int wm, int wn, int l,
                                              int n0, int V, int qidx) {
#pragma unroll
    for (int mt = 0; mt < 4; mt++) {
#pragma unroll
        for (int h = 0; h < 2; h++) {
            int lrow = wm * 64 + mt * 16 + h * 8 + (l >> 2);
            float v0 = NEGINF, v1 = NEGINF; int i0 = -1, i1 = -1;
#pragma unroll
            for (int nt = 0; nt < 8; nt++) {
#pragma unroll
                for (int e = 0; e < 2; e++) {
                    int col = n0 + wn * 64 + nt * 8 + 2 * (l & 3) + e;
                    float v = acc[mt][nt][h * 2 + e];
                    if (MASK && col >= V) v = NEGINF;
                    if (v > v0)      { v1 = v0; i1 = i0; v0 = v; i0 = col; }
                    else if (v > v1) { v1 = v;  i1 = col; }
                }
            }
            Cand c; c.v0 = v0; c.v1 = v1; c.i0 = i0; c.i1 = i1;
            sc[qidx][lrow] = c;
        }
    }
}

__global__ void __launch_bounds__(128, 2)
gemm_hmma_kernel(int V, int NC) {
    extern __shared__ __align__(1024) char smem[];
    const uint32_t sb = smem_u32(smem);

    const int tid = threadIdx.x;          // 128 threads, 4 warps
    const int w   = tid >> 5, l = tid & 31;
    const int wm  = w & 1;                // M half: rows wm*64 .. +63
    const int wn  = w >> 1;               // N half: cols wn*64 .. +63
    const int bx  = blockIdx.x, by = blockIdx.y;
    const int m0  = by * BM, n0 = bx * BN;

    float acc[4][8][4];
#pragma unroll
    for (int i = 0; i < 4; i++)
#pragma unroll
        for (int j = 0; j < 8; j++)
#pragma unroll
            for (int q = 0; q < 4; q++) acc[i][j][q] = 0.0f;

    // ---- cp.async addressing: per-thread cu is constant, rows r0+16i ----
    const int r0 = tid >> 3, cu = tid & 7;
    const uint32_t dof0 = SW128((uint32_t)(r0 * 128 + cu * 16));  // +i*2048 per slot
    const char* pA = (const char*)g_inn_bf16 + (size_t)(m0 + r0) * (D * 2) + cu * 16;
    const char* pB[8];
    uint32_t    szB[8];
#pragma unroll
    for (int i = 0; i < 8; i++) {
        int vr = n0 + r0 + 16 * i;
        int vrc = vr < V ? vr : (V - 1);
        pB[i] = (const char*)g_vnn_bf16 + (size_t)vrc * (D * 2) + cu * 16;
        szB[i] = (vr < V) ? 16u : 0u;
    }

    auto load_chunk = [&](int buf) {
        const uint32_t da = sb + buf * TILE_B;
        const uint32_t db = sb + 32768 + buf * TILE_B;
#pragma unroll
        for (int i = 0; i < 8; i++) CP_ASYNC16(da + dof0 + i * 2048, pA + i * 16384);
#pragma unroll
        for (int i = 0; i < 8; i++) CP_ASYNC16_ZFILL(db + dof0 + i * 2048, pB[i], szB[i]);
        CP_COMMIT();
        pA += 128;
#pragma unroll
        for (int i = 0; i < 8; i++) pB[i] += 128;
    };

    load_chunk(0);

    // ---- hoisted ldmatrix addressing ----
    const int lrow16 = l & 15, khalf = (l >> 4) * 16;
    const uint32_t xorv = (uint32_t)((lrow16 & 7) << 4);
    uint32_t koff[4];
#pragma unroll
    for (int ks = 0; ks < 4; ks++) koff[ks] = ((uint32_t)(ks * 32 + khalf)) ^ xorv;
    uint32_t aRow[4], bRow[4];
#pragma unroll
    for (int mt = 0; mt < 4; mt++) aRow[mt] = (uint32_t)((wm * 64 + mt * 16 + lrow16) * 128);
#pragma unroll
    for (int np = 0; np < 4; np++) bRow[np] = (uint32_t)((wn * 64 + np * 16 + lrow16) * 128);

#pragma unroll 1
    for (int ck = 0; ck < 8; ck++) {
        const int buf = ck & 1;
        if (ck < 7) { load_chunk(buf ^ 1); CP_WAIT(1); }
        else        { CP_WAIT(0); }
        __syncthreads();

        const uint32_t aBase = sb + buf * TILE_B;
        const uint32_t bBase = sb + 32768 + buf * TILE_B;

#pragma unroll
        for (int ks = 0; ks < 4; ks++) {
            uint32_t af[4][4], bf[4][4];
#pragma unroll
            for (int mt = 0; mt < 4; mt++)
                LDMX4(af[mt][0], af[mt][1], af[mt][2], af[mt][3],
                      aBase + aRow[mt] + koff[ks]);
#pragma unroll
            for (int np = 0; np < 4; np++)
                LDMX4(bf[np][0], bf[np][1], bf[np][2], bf[np][3],
                      bBase + bRow[np] + koff[ks]);
            // after the final smem reads of this buffer, release it so next
            // chunk's cp.async can overwrite while remaining MMAs execute.
            if (ks == 3) __syncthreads();
#pragma unroll
            for (int mt = 0; mt < 4; mt++)
#pragma unroll
                for (int nt = 0; nt < 8; nt++) {
                    int np = nt >> 1, hi = nt & 1;
                    MMA16816(acc[mt][nt], af[mt], bf[np][hi], bf[np][hi + 2]);
                }
        }
    }

    // ---- epilogue: transposed Cand table sc[q][row] (16 B row pitch) ----
    Cand (*sc)[128] = reinterpret_cast<Cand (*)[128]>(smem);
    const int qidx = wn * 4 + (l & 3);    // 0..7

    if (n0 + BN <= V) epilogue_topk<false>(acc, sc, wm, wn, l, n0, V, qidx);
    else              epilogue_topk<true >(acc, sc, wm, wn, l, n0, V, qidx);
    __syncthreads();

    // merge 8 partials per row; 128 threads, one row each
    {
        float v0 = NEGINF, v1 = NEGINF; int i0 = -1, i1 = -1;
#pragma unroll 4
        for (int q = 0; q < 8; q++) {
            Cand c = sc[q][tid];            // lanes consecutive 16 B: conflict-free
            if (c.v0 > v0) {
                v1 = v0; i1 = i0; v0 = c.v0; i0 = c.i0;
                if (c.v1 > v1) { v1 = c.v1; i1 = c.i1; }
            } else if (c.v0 > v1) { v1 = c.v0; i1 = c.i0; }
        }
        size_t base = ((size_t)(m0 + tid) * NC + bx) * 2;
        g_cval[base]     = v0; g_cidx[base]     = i0;
        g_cval[base + 1] = v1; g_cidx[base + 1] = i1;
    }
}

// ---------------- merge chunk candidates -> global top-2 per row ----------------
__global__ void reduce_topk_kernel(int NC) {
    __shared__ float sv0[256], sv1[256];
    __shared__ int   si0[256], si1[256];
    int b = blockIdx.x, t = threadIdx.x;
    int n = NC * 2;
    float v0 = NEGINF, v1 = NEGINF; int i0 = -1, i1 = -1;
    size_t base = (size_t)b * NC * 2;
    for (int j = t; j < n; j += 256) {
        float v = g_cval[base + j];
        int  id = g_cidx[base + j];
        if (v > v0)      { v1 = v0; i1 = i0; v0 = v; i0 = id; }
        else if (v > v1) { v1 = v;  i1 = id; }
    }
    sv0[t] = v0; sv1[t] = v1; si0[t] = i0; si1[t] = i1;
    __syncthreads();
    for (int s = 128; s > 0; s >>= 1) {
        if (t < s) {
            float bv0 = sv0[t+s], bv1 = sv1[t+s];
            int   bi0 = si0[t+s], bi1 = si1[t+s];
            float a0 = sv0[t], a1 = sv1[t];
            int   c0 = si0[t], c1 = si1[t];
            if (bv0 > a0) {
                a1 = a0; c1 = c0; a0 = bv0; c0 = bi0;
                if (bv1 > a1) { a1 = bv1; c1 = bi1; }
            } else if (bv0 > a1) { a1 = bv0; c1 = bi0; }
            sv0[t] = a0; sv1[t] = a1; si0[t] = c0; si1[t] = c1;
        }
        __syncthreads();
    }
    if (t == 0) { g_sel[b*2] = si0[0]; g_sel[b*2+1] = si1[0]; }
}

// ---------------- finalize: exact fp32 d_neg + hinge, atomic sum ----------------
__global__ void finalize_kernel(const float* __restrict__ in,
                                const float* __restrict__ tgt,
                                const float* __restrict__ vl,
                                float* __restrict__ out, int Brows) {
    __shared__ float sbuf[5][4];
    int b = blockIdx.x, t = threadIdx.x;   // 128 threads
    int s0 = g_sel[b*2], s1 = g_sel[b*2+1];
    const float4* ip  = (const float4*)(in  + (size_t)b  * D);
    const float4* tp  = (const float4*)(tgt + (size_t)b  * D);
    const float4* v0p = (const float4*)(vl  + (size_t)s0 * D);
    const float4* v1p = (const float4*)(vl  + (size_t)s1 * D);
    float4 iv = ip[t], tv = tp[t], a = v0p[t], c = v1p[t];

    float ii = iv.x*iv.x + iv.y*iv.y + iv.z*iv.z + iv.w*iv.w;
    float ia = iv.x*a.x  + iv.y*a.y  + iv.z*a.z  + iv.w*a.w;
    float aa = a.x*a.x   + a.y*a.y   + a.z*a.z   + a.w*a.w;
    float ic = iv.x*c.x  + iv.y*c.y  + iv.z*c.z  + iv.w*c.w;
    float cc = c.x*c.x   + c.y*c.y   + c.z*c.z   + c.w*c.w;
    int eq = (a.x == tv.x) && (a.y == tv.y) && (a.z == tv.z) && (a.w == tv.w);

    ii = warpSum(ii); ia = warpSum(ia); aa = warpSum(aa);
    ic = warpSum(ic); cc = warpSum(cc);
    int w = t >> 5, l = t & 31;
    if (l == 0) { sbuf[0][w]=ii; sbuf[1][w]=ia; sbuf[2][w]=aa; sbuf[3][w]=ic; sbuf[4][w]=cc; }
    int eq_all = __syncthreads_and(eq);
    if (t == 0) {
        float S[5];
#pragma unroll
        for (int qq = 0; qq < 5; qq++) S[qq] = sbuf[qq][0]+sbuf[qq][1]+sbuf[qq][2]+sbuf[qq][3];
        float ni = fmaxf(sqrtf(S[0]), EPS);
        float dotv, nn2;
        if (eq_all) { dotv = S[3]; nn2 = S[4]; }
        else        { dotv = S[1]; nn2 = S[2]; }
        float nv  = fmaxf(sqrtf(nn2), EPS);
        float sim = dotv / (ni * nv);
        float dneg = sqrtf(fmaxf(2.0f * (1.0f - sim), 1e-12f));
        float margin = 0.5f + g_dpos[b] - dneg;               // GAMMA + d_pos - d_neg
        float h = 2.0f * fmaxf(margin, 0.0f) / (float)Brows;  // RANK * hinge / B
        if (h != 0.0f) atomicAdd(out, h);
        else           atomicAdd(out, 0.0f);
    }
}

__global__ void zero_out_kernel(float* out, int n) {
    int i = blockIdx.x * blockDim.x + threadIdx.x;
    if (i < n) out[i] = 0.0f;
}

extern "C" void kernel_launch(void* const* d_in, const int* in_sizes, int n_in,
                              void* d_out, int out_size) {
    const float* in  = (const float*)d_in[0];
    const float* tgt = (const float*)d_in[1];
    const float* vl  = (const float*)d_in[2];
    float* out = (float*)d_out;

    int Brows = in_sizes[0] / D;      // 4096
    int V     = in_sizes[2] / D;      // 50000
    int NC    = (V + BN - 1) / BN;    // 391

    zero_out_kernel<<<(out_size + 127) / 128, 128>>>(out, out_size);
    prep_input_kernel<<<Brows, 128>>>(in, tgt);
    prep_vec_kernel<<<V, 128>>>(vl, V);

    static int smem_set = 0;
    if (!smem_set) {
        cudaFuncSetAttribute(gemm_hmma_kernel,
                             cudaFuncAttributeMaxDynamicSharedMemorySize, SMEM_BYTES);
        smem_set = 1;
    }
    dim3 ggrid(NC, Brows / BM);
    gemm_hmma_kernel<<<ggrid, 128, SMEM_BYTES>>>(V, NC);

    reduce_topk_kernel<<<Brows, 256>>>(NC);
    finalize_kernel<<<Brows, 128>>>(in, tgt, vl, out, Brows);
}

// round 12
// speedup vs baseline: 7.5876x; 1.0236x over previous
#include <cuda_runtime.h>
#include <cuda_bf16.h>
#include <cstdint>
#include <math.h>

// Fixed shapes: B=4096, D=512, V=50000
#define D      512
#define EPS    1e-8f
#define NEGINF -1e30f
#define BM 128
#define BN 128
#define BK 64
#define MAXB   4096
#define MAXV   50048
#define MAXNC  400

// -------- device-global scratch (no allocations allowed) --------
__device__ __nv_bfloat16 g_inn_bf16[MAXB * D];   // normalized input, bf16 (4 MB)
__device__ __nv_bfloat16 g_vnn_bf16[MAXV * D];   // normalized veclist, bf16 (~51 MB)
__device__ float g_dpos[MAXB];
__device__ float g_cval[MAXB * MAXNC * 2];
__device__ int   g_cidx[MAXB * MAXNC * 2];
__device__ int   g_sel [MAXB * 2];

__device__ __forceinline__ uint32_t smem_u32(const void* p) {
    uint32_t a;
    asm("{ .reg .u64 t; cvta.to.shared.u64 t, %1; cvt.u32.u64 %0, t; }" : "=r"(a) : "l"(p));
    return a;
}
#define SW128(off) ((off) ^ (((off) >> 3) & 0x70))

#define CP_ASYNC16(dst, src) \
    asm volatile("cp.async.cg.shared.global [%0], [%1], 16;" :: "r"(dst), "l"(src))
#define CP_ASYNC16_ZFILL(dst, src, sz) \
    asm volatile("cp.async.cg.shared.global [%0], [%1], 16, %2;" :: "r"(dst), "l"(src), "r"(sz))
#define CP_COMMIT()  asm volatile("cp.async.commit_group;" ::: "memory")
#define CP_WAIT(n)   asm volatile("cp.async.wait_group %0;" :: "n"(n) : "memory")

#define LDMX4(r0, r1, r2, r3, addr) \
    asm volatile("ldmatrix.sync.aligned.m8n8.x4.shared.b16 {%0,%1,%2,%3}, [%4];" \
                 : "=r"(r0), "=r"(r1), "=r"(r2), "=r"(r3) : "r"(addr))

#define MMA16816(d, a, b0, b1) \
    asm volatile("mma.sync.aligned.m16n8k16.row.col.f32.bf16.bf16.f32 " \
                 "{%0,%1,%2,%3}, {%4,%5,%6,%7}, {%8,%9}, {%0,%1,%2,%3};" \
                 : "+f"((d)[0]), "+f"((d)[1]), "+f"((d)[2]), "+f"((d)[3]) \
                 : "r"((a)[0]), "r"((a)[1]), "r"((a)[2]), "r"((a)[3]), \
                   "r"(b0), "r"(b1))

__device__ __forceinline__ float warpSum(float v) {
#pragma unroll
    for (int o = 16; o > 0; o >>= 1) v += __shfl_down_sync(0xffffffffu, v, o);
    return v;
}

// ---------------- prep: normalize input rows -> bf16, compute d_pos ----------------
__global__ void prep_input_kernel(const float* __restrict__ in,
                                  const float* __restrict__ tgt) {
    __shared__ float sbuf[3][4];
    int b = blockIdx.x, t = threadIdx.x;  // 128 threads
    const float4* ip = (const float4*)(in  + (size_t)b * D);
    const float4* tp = (const float4*)(tgt + (size_t)b * D);
    float4 iv = ip[t], tv = tp[t];
    float ii = iv.x*iv.x + iv.y*iv.y + iv.z*iv.z + iv.w*iv.w;
    float tt = tv.x*tv.x + tv.y*tv.y + tv.z*tv.z + tv.w*tv.w;
    float it = iv.x*tv.x + iv.y*tv.y + iv.z*tv.z + iv.w*tv.w;
    ii = warpSum(ii); tt = warpSum(tt); it = warpSum(it);
    int w = t >> 5, l = t & 31;
    if (l == 0) { sbuf[0][w] = ii; sbuf[1][w] = tt; sbuf[2][w] = it; }
    __syncthreads();
    float s_ii = sbuf[0][0]+sbuf[0][1]+sbuf[0][2]+sbuf[0][3];
    float s_tt = sbuf[1][0]+sbuf[1][1]+sbuf[1][2]+sbuf[1][3];
    float s_it = sbuf[2][0]+sbuf[2][1]+sbuf[2][2]+sbuf[2][3];
    float ni = fmaxf(sqrtf(s_ii), EPS);
    float inv = 1.0f / ni;
    __nv_bfloat162* op = (__nv_bfloat162*)(g_inn_bf16 + (size_t)b * D);
    op[t*2]   = __floats2bfloat162_rn(iv.x*inv, iv.y*inv);
    op[t*2+1] = __floats2bfloat162_rn(iv.z*inv, iv.w*inv);
    if (t == 0) {
        float nt  = fmaxf(sqrtf(s_tt), EPS);
        float sim = s_it / (ni * nt);
        g_dpos[b] = sqrtf(fmaxf(2.0f * (1.0f - sim), 1e-12f));
    }
}

// ---------------- prep: normalize veclist rows -> bf16 ----------------
__global__ void prep_vec_kernel(const float* __restrict__ vl, int V) {
    __shared__ float sbuf[4];
    int v = blockIdx.x;
    if (v >= V) return;
    int t = threadIdx.x;  // 128 threads
    const float4* vp = (const float4*)(vl + (size_t)v * D);
    float4 x = vp[t];
    float nn = x.x*x.x + x.y*x.y + x.z*x.z + x.w*x.w;
    nn = warpSum(nn);
    int w = t >> 5, l = t & 31;
    if (l == 0) sbuf[w] = nn;
    __syncthreads();
    float s = sbuf[0]+sbuf[1]+sbuf[2]+sbuf[3];
    float inv = 1.0f / fmaxf(sqrtf(s), EPS);
    __nv_bfloat162* op = (__nv_bfloat162*)(g_vnn_bf16 + (size_t)v * D);
    op[t*2]   = __floats2bfloat162_rn(x.x*inv, x.y*inv);
    op[t*2+1] = __floats2bfloat162_rn(x.z*inv, x.w*inv);
}

// ---------------- HMMA GEMM + fused per-tile top-2 ----------------
struct Cand { float v0, v1; int i0, i1; };

// merge two top-2 structs (tournament node)
__device__ __forceinline__ Cand t2_merge(Cand a, Cand b) {
    Cand r;
    if (b.v0 > a.v0) {
        r.v0 = b.v0; r.i0 = b.i0;
        bool c = a.v0 > b.v1;
        r.v1 = c ? a.v0 : b.v1; r.i1 = c ? a.i0 : b.i1;
    } else {
        r.v0 = a.v0; r.i0 = a.i0;
        bool c = b.v0 > a.v1;
        r.v1 = c ? b.v0 : a.v1; r.i1 = c ? b.i0 : a.i1;
    }
    return r;
}

// dynamic SMEM layout (64 KB):
//   A bufs: 2 x 16 KB at 0, 16384      (128 rows x 64 bf16, SW128)
//   B bufs: 2 x 16 KB at 32768, 49152  (128 rows x 64 bf16, SW128)
//   Cand table sc[8][128] (16 KB) aliases A bufs after the mainloop.
#define SMEM_BYTES 65536
#define TILE_B     16384

// per-thread top-2 via tournament tree; MASK = tail tile only
template <bool MASK>
__device__ __forceinline__ void epilogue_topk(const float acc[4][8][4],
                                              Cand (*sc)[128],
                                              int wm, int wn, int l,
                                              int n0, int V, int qidx) {
    const int cb = n0 + wn * 64 + 2 * (l & 3);
#pragma unroll
    for (int mt = 0; mt < 4; mt++) {
#pragma unroll
        for (int h = 0; h < 2; h++) {
            int lrow = wm * 64 + mt * 16 + h * 8 + (l >> 2);
            // 8 leaves: ordered pairs (e=0, e=1) per nt
            Cand t[8];
#pragma unroll
            for (int nt = 0; nt < 8; nt++) {
                float p0 = acc[mt][nt][h * 2 + 0];
                float p1 = acc[mt][nt][h * 2 + 1];
                int   c0 = cb + nt * 8, c1 = c0 + 1;
                if (MASK) {
                    if (c0 >= V) p0 = NEGINF;
                    if (c1 >= V) p1 = NEGINF;
                }
                bool sw = p1 > p0;
                t[nt].v0 = sw ? p1 : p0; t[nt].i0 = sw ? c1 : c0;
                t[nt].v1 = sw ? p0 : p1; t[nt].i1 = sw ? c0 : c1;
            }
            // tournament: 8 -> 4 -> 2 -> 1 (independent subtrees, good ILP)
            Cand m0 = t2_merge(t[0], t[1]);
            Cand m1 = t2_merge(t[2], t[3]);
            Cand m2 = t2_merge(t[4], t[5]);
            Cand m3 = t2_merge(t[6], t[7]);
            Cand n0c = t2_merge(m0, m1);
            Cand n1c = t2_merge(m2, m3);
            sc[qidx][lrow] = t2_merge(n0c, n1c);
        }
    }
}

__global__ void __launch_bounds__(128, 2)
gemm_hmma_kernel(int V, int NC) {
    extern __shared__ __align__(1024) char smem[];
    const uint32_t sb = smem_u32(smem);

    const int tid = threadIdx.x;          // 128 threads, 4 warps
    const int w   = tid >> 5, l = tid & 31;
    const int wm  = w & 1;                // M half: rows wm*64 .. +63
    const int wn  = w >> 1;               // N half: cols wn*64 .. +63
    const int bx  = blockIdx.x, by = blockIdx.y;
    const int m0  = by * BM, n0 = bx * BN;

    float acc[4][8][4];
#pragma unroll
    for (int i = 0; i < 4; i++)
#pragma unroll
        for (int j = 0; j < 8; j++)
#pragma unroll
            for (int q = 0; q < 4; q++) acc[i][j][q] = 0.0f;

    // ---- cp.async addressing: per-thread cu is constant, rows r0+16i ----
    const int r0 = tid >> 3, cu = tid & 7;
    const uint32_t dof0 = SW128((uint32_t)(r0 * 128 + cu * 16));  // +i*2048 per slot
    const char* pA = (const char*)g_inn_bf16 + (size_t)(m0 + r0) * (D * 2) + cu * 16;
    const char* pB[8];
    uint32_t    szB[8];
#pragma unroll
    for (int i = 0; i < 8; i++) {
        int vr = n0 + r0 + 16 * i;
        int vrc = vr < V ? vr : (V - 1);
        pB[i] = (const char*)g_vnn_bf16 + (size_t)vrc * (D * 2) + cu * 16;
        szB[i] = (vr < V) ? 16u : 0u;
    }

    auto load_chunk = [&](int buf) {
        const uint32_t da = sb + buf * TILE_B;
        const uint32_t db = sb + 32768 + buf * TILE_B;
#pragma unroll
        for (int i = 0; i < 8; i++) CP_ASYNC16(da + dof0 + i * 2048, pA + i * 16384);
#pragma unroll
        for (int i = 0; i < 8; i++) CP_ASYNC16_ZFILL(db + dof0 + i * 2048, pB[i], szB[i]);
        CP_COMMIT();
        pA += 128;
#pragma unroll
        for (int i = 0; i < 8; i++) pB[i] += 128;
    };

    load_chunk(0);

    // ---- hoisted ldmatrix addressing ----
    const int lrow16 = l & 15, khalf = (l >> 4) * 16;
    const uint32_t xorv = (uint32_t)((lrow16 & 7) << 4);
    uint32_t koff[4];
#pragma unroll
    for (int ks = 0; ks < 4; ks++) koff[ks] = ((uint32_t)(ks * 32 + khalf)) ^ xorv;
    uint32_t aRow[4], bRow[4];
#pragma unroll
    for (int mt = 0; mt < 4; mt++) aRow[mt] = (uint32_t)((wm * 64 + mt * 16 + lrow16) * 128);
#pragma unroll
    for (int np = 0; np < 4; np++) bRow[np] = (uint32_t)((wn * 64 + np * 16 + lrow16) * 128);

    // double-buffered fragment registers (software pipeline over ks)
    uint32_t afr[2][4][4], bfr[2][4][4];

#pragma unroll 1
    for (int ck = 0; ck < 8; ck++) {
        const int buf = ck & 1;
        if (ck < 7) { load_chunk(buf ^ 1); CP_WAIT(1); }
        else        { CP_WAIT(0); }
        __syncthreads();

        const uint32_t aBase = sb + buf * TILE_B;
        const uint32_t bBase = sb + 32768 + buf * TILE_B;

        // prefetch ks=0 fragments
#pragma unroll
        for (int mt = 0; mt < 4; mt++)
            LDMX4(afr[0][mt][0], afr[0][mt][1], afr[0][mt][2], afr[0][mt][3],
                  aBase + aRow[mt] + koff[0]);
#pragma unroll
        for (int np = 0; np < 4; np++)
            LDMX4(bfr[0][np][0], bfr[0][np][1], bfr[0][np][2], bfr[0][np][3],
                  bBase + bRow[np] + koff[0]);

#pragma unroll
        for (int ks = 0; ks < 4; ks++) {
            const int cur = ks & 1, nxt = cur ^ 1;
            if (ks < 3) {
                // prefetch next ks fragments while this ks's MMAs execute
#pragma unroll
                for (int mt = 0; mt < 4; mt++)
                    LDMX4(afr[nxt][mt][0], afr[nxt][mt][1], afr[nxt][mt][2], afr[nxt][mt][3],
                          aBase + aRow[mt] + koff[ks + 1]);
#pragma unroll
                for (int np = 0; np < 4; np++)
                    LDMX4(bfr[nxt][np][0], bfr[nxt][np][1], bfr[nxt][np][2], bfr[nxt][np][3],
                          bBase + bRow[np] + koff[ks + 1]);
            }
            // after the LAST smem reads of this buffer (ks=3 frags prefetched
            // during ks=2), release it: ks=2 and ks=3 MMAs (register-only)
            // overlap the next chunk's cp.async issue.
            if (ks == 2) __syncthreads();
#pragma unroll
            for (int mt = 0; mt < 4; mt++)
#pragma unroll
                for (int nt = 0; nt < 8; nt++) {
                    int np = nt >> 1, hi = nt & 1;
                    MMA16816(acc[mt][nt], afr[cur][mt],
                             bfr[cur][np][hi], bfr[cur][np][hi + 2]);
                }
        }
    }

    // ---- epilogue: transposed Cand table sc[q][row] (16 B row pitch) ----
    Cand (*sc)[128] = reinterpret_cast<Cand (*)[128]>(smem);
    const int qidx = wn * 4 + (l & 3);    // 0..7

    if (n0 + BN <= V) epilogue_topk<false>(acc, sc, wm, wn, l, n0, V, qidx);
    else              epilogue_topk<true >(acc, sc, wm, wn, l, n0, V, qidx);
    __syncthreads();

    // merge 8 partials per row; 128 threads, one row each
    {
        float v0 = NEGINF, v1 = NEGINF; int i0 = -1, i1 = -1;
#pragma unroll 4
        for (int q = 0; q < 8; q++) {
            Cand c = sc[q][tid];            // lanes consecutive 16 B: conflict-free
            if (c.v0 > v0) {
                v1 = v0; i1 = i0; v0 = c.v0; i0 = c.i0;
                if (c.v1 > v1) { v1 = c.v1; i1 = c.i1; }
            } else if (c.v0 > v1) { v1 = c.v0; i1 = c.i0; }
        }
        size_t base = ((size_t)(m0 + tid) * NC + bx) * 2;
        g_cval[base]     = v0; g_cidx[base]     = i0;
        g_cval[base + 1] = v1; g_cidx[base + 1] = i1;
    }
}

// ---------------- merge chunk candidates -> global top-2 per row ----------------
__global__ void reduce_topk_kernel(int NC) {
    __shared__ float sv0[256], sv1[256];
    __shared__ int   si0[256], si1[256];
    int b = blockIdx.x, t = threadIdx.x;
    int n = NC * 2;
    float v0 = NEGINF, v1 = NEGINF; int i0 = -1, i1 = -1;
    size_t base = (size_t)b * NC * 2;
    for (int j = t; j < n; j += 256) {
        float v = g_cval[base + j];
        int  id = g_cidx[base + j];
        if (v > v0)      { v1 = v0; i1 = i0; v0 = v; i0 = id; }
        else if (v > v1) { v1 = v;  i1 = id; }
    }
    sv0[t] = v0; sv1[t] = v1; si0[t] = i0; si1[t] = i1;
    __syncthreads();
    for (int s = 128; s > 0; s >>= 1) {
        if (t < s) {
            float bv0 = sv0[t+s], bv1 = sv1[t+s];
            int   bi0 = si0[t+s], bi1 = si1[t+s];
            float a0 = sv0[t], a1 = sv1[t];
            int   c0 = si0[t], c1 = si1[t];
            if (bv0 > a0) {
                a1 = a0; c1 = c0; a0 = bv0; c0 = bi0;
                if (bv1 > a1) { a1 = bv1; c1 = bi1; }
            } else if (bv0 > a1) { a1 = bv0; c1 = bi0; }
            sv0[t] = a0; sv1[t] = a1; si0[t] = c0; si1[t] = c1;
        }
        __syncthreads();
    }
    if (t == 0) { g_sel[b*2] = si0[0]; g_sel[b*2+1] = si1[0]; }
}

// ---------------- finalize: exact fp32 d_neg + hinge, atomic sum ----------------
__global__ void finalize_kernel(const float* __restrict__ in,
                                const float* __restrict__ tgt,
                                const float* __restrict__ vl,
                                float* __restrict__ out, int Brows) {
    __shared__ float sbuf[5][4];
    int b = blockIdx.x, t = threadIdx.x;   // 128 threads
    int s0 = g_sel[b*2], s1 = g_sel[b*2+1];
    const float4* ip  = (const float4*)(in  + (size_t)b  * D);
    const float4* tp  = (const float4*)(tgt + (size_t)b  * D);
    const float4* v0p = (const float4*)(vl  + (size_t)s0 * D);
    const float4* v1p = (const float4*)(vl  + (size_t)s1 * D);
    float4 iv = ip[t], tv = tp[t], a = v0p[t], c = v1p[t];

    float ii = iv.x*iv.x + iv.y*iv.y + iv.z*iv.z + iv.w*iv.w;
    float ia = iv.x*a.x  + iv.y*a.y  + iv.z*a.z  + iv.w*a.w;
    float aa = a.x*a.x   + a.y*a.y   + a.z*a.z   + a.w*a.w;
    float ic = iv.x*c.x  + iv.y*c.y  + iv.z*c.z  + iv.w*c.w;
    float cc = c.x*c.x   + c.y*c.y   + c.z*c.z   + c.w*c.w;
    int eq = (a.x == tv.x) && (a.y == tv.y) && (a.z == tv.z) && (a.w == tv.w);

    ii = warpSum(ii); ia = warpSum(ia); aa = warpSum(aa);
    ic = warpSum(ic); cc = warpSum(cc);
    int w = t >> 5, l = t & 31;
    if (l == 0) { sbuf[0][w]=ii; sbuf[1][w]=ia; sbuf[2][w]=aa; sbuf[3][w]=ic; sbuf[4][w]=cc; }
    int eq_all = __syncthreads_and(eq);
    if (t == 0) {
        float S[5];
#pragma unroll
        for (int qq = 0; qq < 5; qq++) S[qq] = sbuf[qq][0]+sbuf[qq][1]+sbuf[qq][2]+sbuf[qq][3];
        float ni = fmaxf(sqrtf(S[0]), EPS);
        float dotv, nn2;
        if (eq_all) { dotv = S[3]; nn2 = S[4]; }
        else        { dotv = S[1]; nn2 = S[2]; }
        float nv  = fmaxf(sqrtf(nn2), EPS);
        float sim = dotv / (ni * nv);
        float dneg = sqrtf(fmaxf(2.0f * (1.0f - sim), 1e-12f));
        float margin = 0.5f + g_dpos[b] - dneg;               // GAMMA + d_pos - d_neg
        float h = 2.0f * fmaxf(margin, 0.0f) / (float)Brows;  // RANK * hinge / B
        if (h != 0.0f) atomicAdd(out, h);
        else           atomicAdd(out, 0.0f);
    }
}

__global__ void zero_out_kernel(float* out, int n) {
    int i = blockIdx.x * blockDim.x + threadIdx.x;
    if (i < n) out[i] = 0.0f;
}

extern "C" void kernel_launch(void* const* d_in, const int* in_sizes, int n_in,
                              void* d_out, int out_size) {
    const float* in  = (const float*)d_in[0];
    const float* tgt = (const float*)d_in[1];
    const float* vl  = (const float*)d_in[2];
    float* out = (float*)d_out;

    int Brows = in_sizes[0] / D;      // 4096
    int V     = in_sizes[2] / D;      // 50000
    int NC    = (V + BN - 1) / BN;    // 391

    zero_out_kernel<<<(out_size + 127) / 128, 128>>>(out, out_size);
    prep_input_kernel<<<Brows, 128>>>(in, tgt);
    prep_vec_kernel<<<V, 128>>>(vl, V);

    static int smem_set = 0;
    if (!smem_set) {
        cudaFuncSetAttribute(gemm_hmma_kernel,
                             cudaFuncAttributeMaxDynamicSharedMemorySize, SMEM_BYTES);
        smem_set = 1;
    }
    dim3 ggrid(NC, Brows / BM);
    gemm_hmma_kernel<<<ggrid, 128, SMEM_BYTES>>>(V, NC);

    reduce_topk_kernel<<<Brows, 256>>>(NC);
    finalize_kernel<<<Brows, 128>>>(in, tgt, vl, out, Brows);
}